// round 10
// baseline (speedup 1.0000x reference)
#include <cuda_runtime.h>
#include <cstdint>

#define NT      215     // number of (l1,l2,l) triples
#define NCOEF   81      // (LMAX+1)^2
#define TPB     512     // threads per CTA = batch rows per CTA (R=1)
#define ROWS    512     // batch rows per CTA
#define XS      513     // padded row stride of transposed x tile
#define XT_FL   41556   // 81*513 = 41553, rounded up to multiple of 4 floats
#define MAXC    5780    // 17*17*20 floats: max padded compact C block

// ---------------------------------------------------------------------------
// helpers
// ---------------------------------------------------------------------------
__device__ __forceinline__ unsigned smem_addr_u32(const void* p) {
    unsigned r;
    asm("{ .reg .u64 t; cvta.to.shared.u64 t, %1; cvt.u32.u64 %0, t; }"
        : "=r"(r) : "l"(p));
    return r;
}

__device__ __forceinline__ void cp_async4(unsigned dst, const float* src) {
    asm volatile("cp.async.ca.shared.global [%0], [%1], 4;" :: "r"(dst), "l"(src));
}

__device__ __forceinline__ void cp_commit() {
    asm volatile("cp.async.commit_group;" ::: "memory");
}

__device__ __forceinline__ void cp_wait_all() {
    asm volatile("cp.async.wait_group 0;" ::: "memory");
}

#define FMA2(acc, a, b)  asm("fma.rn.f32x2 %0, %1, %2, %0;" : "+l"(acc) : "l"(a), "l"(b))
#define PACK2(d, lo, hi) asm("mov.b64 %0, {%1, %2};" : "=l"(d) : "f"(lo), "f"(hi))
#define DUP2(d, v)       asm("mov.b64 %0, {%1, %1};" : "=l"(d) : "f"(v))

// ---------------------------------------------------------------------------
// Per-triple contraction, ONE batch row per thread (R=1; warps provide the
// latency hiding at 4 warps/SMSP).
//   beta = sum_{i<d1, j<d2, k<D3} C[i][j][k] * F1[i] * F2[j] * F3[k]
// C rows padded to P4*4 floats (pad slots finite; nullified by zero F3 pack
// halves). f1 hoisted out of the j-loop (per-i fold).
// ---------------------------------------------------------------------------
template<int D3>
__device__ __forceinline__ float compute_triple1(const float* xT, const float* Cs,
                                                 int l1s, int l2s, int ls,
                                                 int d1, int d2, int tid)
{
    constexpr int P4 = (D3 + 3) / 4;   // float4 groups per C row
    constexpr int NP = 2 * P4;         // f32x2 packs per C row
    constexpr int RS = 4 * P4;         // row stride in floats

    // Packed F3 (zero-padded past D3)
    unsigned long long fp[NP];
#pragma unroll
    for (int q = 0; q < NP; q++) {
        const float* b0 = xT + (ls + 2 * q) * XS + tid;
        float a0 = (2 * q     < D3) ? b0[0]  : 0.0f;
        float a1 = (2 * q + 1 < D3) ? b0[XS] : 0.0f;
        PACK2(fp[q], a0, a1);
    }

    unsigned long long acc = 0ULL;
    const float* p1 = xT + l1s * XS + tid;
    const float* ci = Cs;
    const int ci_stride = d2 * RS;

    for (int i = 0; i < d1; i++, p1 += XS, ci += ci_stride) {
        unsigned long long ia = 0ULL;          // per-i accumulator
        const float* p2 = xT + l2s * XS + tid;
        const float* cr = ci;

        for (int j = 0; j < d2; j++, p2 += XS, cr += RS) {
            unsigned long long sa = 0ULL, sb = 0ULL;   // 2 chains
#pragma unroll
            for (int q = 0; q < P4; q++) {
                float4 c4 = ((const float4*)cr)[q];    // LDS.128 broadcast
                unsigned long long c01, c23;
                PACK2(c01, c4.x, c4.y);
                PACK2(c23, c4.z, c4.w);
                FMA2(sa, c01, fp[2 * q]);
                FMA2(sb, c23, fp[2 * q + 1]);
            }
            unsigned long long d2p;
            DUP2(d2p, p2[0]);
            FMA2(ia, sa, d2p);
            FMA2(ia, sb, d2p);
        }

        unsigned long long d1p;
        DUP2(d1p, p1[0]);
        FMA2(acc, ia, d1p);
    }

    float alo, ahi;
    asm("mov.b64 {%0, %1}, %2;" : "=f"(alo), "=f"(ahi) : "l"(acc));
    return alo + ahi;
}

// ---------------------------------------------------------------------------
// Stage compact C block of triple t into smem (rows padded to 4 floats) via
// 4-byte cp.async. Magic-multiply division; divisor==1 cases (magic
// truncates to 0) handled by uniform branch.
// ---------------------------------------------------------------------------
__device__ __forceinline__ void stage_triple(int t, float* buf, const float* cg,
                                             const int* tb_d1, const int* tb_d2,
                                             const int* tb_d3,
                                             const unsigned* tb_m23,
                                             const unsigned* tb_m3, int tid)
{
    int d2  = tb_d2[t], d3 = tb_d3[t];
    int d23 = d2 * d3;
    int total = tb_d1[t] * d23;
    unsigned m23 = tb_m23[t], m3 = tb_m3[t];
    int p4f = (d3 + 3) & ~3;
    const float* src = cg + (size_t)t * (17 * 17 * 17);
    unsigned sbase = smem_addr_u32(buf);

    bool d23_one = (d23 == 1);
    bool d3_one  = (d3 == 1);

    for (int e = tid; e < total; e += TPB) {
        int i   = d23_one ? e : (int)__umulhi((unsigned)e, m23);
        int rem = e - i * d23;
        int j   = d3_one ? rem : (int)__umulhi((unsigned)rem, m3);
        int k   = rem - j * d3;
        unsigned dst = sbase + (unsigned)(((i * d2 + j) * p4f + k) << 2);
        cp_async4(dst, src + i * 289 + j * 17 + k);
    }
}

// ---------------------------------------------------------------------------
// Main kernel
// ---------------------------------------------------------------------------
extern __shared__ char smem_raw[];

__global__ void __launch_bounds__(TPB, 1)
bispec_kernel(const float* __restrict__ x, const float* __restrict__ cg,
              float* __restrict__ out, int B)
{
    float* xT  = (float*)smem_raw;          // [81][513] transposed x tile (512 rows)
    float* cb0 = xT + XT_FL;                // C double buffer
    float* cb1 = cb0 + MAXC;
    int*   tb  = (int*)(cb1 + MAXC);        // triple table (8 arrays of NT)
    int* tb_l1s = tb;
    int* tb_l2s = tb + NT;
    int* tb_ls  = tb + 2 * NT;
    int* tb_d1  = tb + 3 * NT;
    int* tb_d2  = tb + 4 * NT;
    int* tb_d3  = tb + 5 * NT;
    unsigned* tb_m23 = (unsigned*)(tb + 6 * NT);
    unsigned* tb_m3  = (unsigned*)(tb + 7 * NT);

    const int tid = threadIdx.x;
    const int b0  = blockIdx.x * ROWS;

    // Build triple table (must match reference enumeration order)
    if (tid == 0) {
        int n = 0;
        for (int l1 = 0; l1 <= 8; l1++)
            for (int l2 = l1; l2 <= 8; l2++) {
                int lhi = (l1 + l2 < 8) ? (l1 + l2) : 8;
                for (int l = l2 - l1; l <= lhi; l++) {
                    tb_l1s[n] = l1 * l1; tb_l2s[n] = l2 * l2; tb_ls[n] = l * l;
                    int d1 = 2 * l1 + 1, d2 = 2 * l2 + 1, d3 = 2 * l + 1;
                    tb_d1[n] = d1; tb_d2[n] = d2; tb_d3[n] = d3;
                    unsigned d23 = (unsigned)(d2 * d3);
                    // divisor==1 -> magic truncates to 0; stage_triple branches that case
                    tb_m23[n] = (unsigned)((0x100000000ULL + d23 - 1) / d23);
                    tb_m3[n]  = (unsigned)((0x100000000ULL + (unsigned)d3 - 1) / (unsigned)d3);
                    n++;
                }
            }
    }

    // Zero C buffers once: pad slots must always read finite (later they hold
    // stale cg floats, nullified by the zero F3 pack halves)
    for (int i = tid; i < 2 * MAXC; i += TPB) cb0[i] = 0.0f;

    // Stage x tile transposed: xT[c][r] = x[b0+r][c]
    for (int idx = tid; idx < NCOEF * ROWS; idx += TPB) {
        int r = idx / NCOEF;
        int c = idx - r * NCOEF;
        float v = (b0 + r < B) ? x[(size_t)b0 * NCOEF + idx] : 0.0f;
        xT[c * XS + r] = v;
    }
    __syncthreads();

    // Prime the C pipeline
    stage_triple(0, cb0, cg, tb_d1, tb_d2, tb_d3, tb_m23, tb_m3, tid);
    cp_commit();
    cp_wait_all();
    __syncthreads();

    const size_t ob = (size_t)(b0 + tid) * NT;
    const bool   vv = (b0 + tid < B);

    for (int t = 0; t < NT; t++) {
        float* cur = (t & 1) ? cb1 : cb0;
        float* nxt = (t & 1) ? cb0 : cb1;

        if (t + 1 < NT)
            stage_triple(t + 1, nxt, cg, tb_d1, tb_d2, tb_d3, tb_m23, tb_m3, tid);
        cp_commit();

        int l1s = tb_l1s[t], l2s = tb_l2s[t], ls = tb_ls[t];
        int d1 = tb_d1[t], d2 = tb_d2[t], d3 = tb_d3[t];

        float acc;
        switch (d3) {
            case 1:  acc = compute_triple1< 1>(xT, cur, l1s, l2s, ls, d1, d2, tid); break;
            case 3:  acc = compute_triple1< 3>(xT, cur, l1s, l2s, ls, d1, d2, tid); break;
            case 5:  acc = compute_triple1< 5>(xT, cur, l1s, l2s, ls, d1, d2, tid); break;
            case 7:  acc = compute_triple1< 7>(xT, cur, l1s, l2s, ls, d1, d2, tid); break;
            case 9:  acc = compute_triple1< 9>(xT, cur, l1s, l2s, ls, d1, d2, tid); break;
            case 11: acc = compute_triple1<11>(xT, cur, l1s, l2s, ls, d1, d2, tid); break;
            case 13: acc = compute_triple1<13>(xT, cur, l1s, l2s, ls, d1, d2, tid); break;
            case 15: acc = compute_triple1<15>(xT, cur, l1s, l2s, ls, d1, d2, tid); break;
            default: acc = compute_triple1<17>(xT, cur, l1s, l2s, ls, d1, d2, tid); break;
        }

        // Direct scattered stores: ~450MB L2 sector traffic total, hidden
        // under >2ms of compute.
        if (vv) out[ob + t] = acc;

        cp_wait_all();
        __syncthreads();
    }
}

// ---------------------------------------------------------------------------
// Entry point
// ---------------------------------------------------------------------------
extern "C" void kernel_launch(void* const* d_in, const int* in_sizes, int n_in,
                              void* d_out, int out_size)
{
    const float* x  = (const float*)d_in[0];
    const float* cg = (const float*)d_in[1];
    float* out = (float*)d_out;

    int B = in_sizes[0] / NCOEF;
    int grid = (B + ROWS - 1) / ROWS;

    size_t smem_bytes = (size_t)(XT_FL + 2 * MAXC) * sizeof(float)
                      + (size_t)8 * NT * sizeof(int);   // = 219,344 B

    cudaFuncSetAttribute(bispec_kernel,
                         cudaFuncAttributeMaxDynamicSharedMemorySize,
                         (int)smem_bytes);

    bispec_kernel<<<grid, TPB, smem_bytes>>>(x, cg, out, B);
}

// round 12
// speedup vs baseline: 1.2208x; 1.2208x over previous
#include <cuda_runtime.h>
#include <cstdint>

#define NT      215     // number of (l1,l2,l) triples
#define NCOEF   81      // (LMAX+1)^2
#define TPB     256     // threads per CTA
#define ROWS    512     // batch rows per CTA = 2*TPB (R=2 register blocking)
#define XS      513     // padded row stride of transposed x tile
#define XT_FL   41556   // 81*513 = 41553, rounded up to multiple of 4 floats
#define MAXC    5780    // 17*17*20 floats: max padded compact C block

// ---------------------------------------------------------------------------
// helpers
// ---------------------------------------------------------------------------
__device__ __forceinline__ unsigned smem_addr_u32(const void* p) {
    unsigned r;
    asm("{ .reg .u64 t; cvta.to.shared.u64 t, %1; cvt.u32.u64 %0, t; }"
        : "=r"(r) : "l"(p));
    return r;
}

__device__ __forceinline__ void cp_async4(unsigned dst, const float* src) {
    asm volatile("cp.async.ca.shared.global [%0], [%1], 4;" :: "r"(dst), "l"(src));
}

__device__ __forceinline__ void cp_commit() {
    asm volatile("cp.async.commit_group;" ::: "memory");
}

__device__ __forceinline__ void cp_wait_all() {
    asm volatile("cp.async.wait_group 0;" ::: "memory");
}

#define FMA2(acc, a, b)  asm("fma.rn.f32x2 %0, %1, %2, %0;" : "+l"(acc) : "l"(a), "l"(b))
#define ADD2(d, a, b)    asm("add.rn.f32x2 %0, %1, %2;"     : "=l"(d)  : "l"(a), "l"(b))
#define PACK2(d, lo, hi) asm("mov.b64 %0, {%1, %2};" : "=l"(d) : "f"(lo), "f"(hi))
#define DUP2(d, v)       asm("mov.b64 %0, {%1, %1};" : "=l"(d) : "f"(v))

// ---------------------------------------------------------------------------
// General per-triple contraction, TWO batch rows per thread (R=2).
//   beta = sum_{i<d1, j<d2, k<D3} C[i][j][k] * F1[i] * F2[j] * F3[k]
// C rows padded to P4*4 floats (pad slots finite; nullified by zero F3 pack
// halves). f1 hoisted (per-i fold).
// ---------------------------------------------------------------------------
template<int D3>
__device__ __forceinline__ void compute_gen(const float* xT, const float* Cs,
                                            int l1s, int l2s, int ls,
                                            int d1, int d2, int tid,
                                            float& out_a, float& out_b)
{
    constexpr int P4 = (D3 + 3) / 4;
    constexpr int NP = 2 * P4;
    constexpr int RS = 4 * P4;

    unsigned long long fa[NP], fb[NP];
#pragma unroll
    for (int q = 0; q < NP; q++) {
        const float* b0 = xT + (ls + 2 * q) * XS + tid;
        float a0 = (2 * q     < D3) ? b0[0]        : 0.0f;
        float a1 = (2 * q + 1 < D3) ? b0[XS]       : 0.0f;
        float v0 = (2 * q     < D3) ? b0[TPB]      : 0.0f;
        float v1 = (2 * q + 1 < D3) ? b0[XS + TPB] : 0.0f;
        PACK2(fa[q], a0, a1);
        PACK2(fb[q], v0, v1);
    }

    unsigned long long acc_a = 0ULL, acc_b = 0ULL;
    const float* p1 = xT + l1s * XS + tid;
    const float* ci = Cs;
    const int ci_stride = d2 * RS;

    for (int i = 0; i < d1; i++, p1 += XS, ci += ci_stride) {
        unsigned long long ia = 0ULL, ib = 0ULL;
        const float* p2 = xT + l2s * XS + tid;
        const float* cr = ci;

        for (int j = 0; j < d2; j++, p2 += XS, cr += RS) {
            unsigned long long saa = 0, sba = 0, sab = 0, sbb = 0;
#pragma unroll
            for (int q = 0; q < P4; q++) {
                float4 c4 = ((const float4*)cr)[q];   // LDS.128 broadcast
                unsigned long long c01, c23;
                PACK2(c01, c4.x, c4.y);
                PACK2(c23, c4.z, c4.w);
                FMA2(saa, c01, fa[2 * q]);
                FMA2(sab, c01, fb[2 * q]);
                FMA2(sba, c23, fa[2 * q + 1]);
                FMA2(sbb, c23, fb[2 * q + 1]);
            }
            unsigned long long da, db;
            DUP2(da, p2[0]);
            DUP2(db, p2[TPB]);
            FMA2(ia, saa, da);
            FMA2(ia, sba, da);
            FMA2(ib, sab, db);
            FMA2(ib, sbb, db);
        }

        unsigned long long d1a, d1b;
        DUP2(d1a, p1[0]);
        DUP2(d1b, p1[TPB]);
        FMA2(acc_a, ia, d1a);
        FMA2(acc_b, ib, d1b);
    }

    float alo, ahi, blo, bhi;
    asm("mov.b64 {%0, %1}, %2;" : "=f"(alo), "=f"(ahi) : "l"(acc_a));
    asm("mov.b64 {%0, %1}, %2;" : "=f"(blo), "=f"(bhi) : "l"(acc_b));
    out_a = alo + ahi;
    out_b = blo + bhi;
}

// ---------------------------------------------------------------------------
// Diagonal-triple contraction (l1 == l2, so F1 == F2 == F). Symmetrized:
//   beta = sum_i F_i * [ C(i,i)·F3·F_i + sum_{j>i} (C(i,j)+C(j,i))·F3·F_j ]
// Exact algebra (reassociation only). Halves the (i,j) pair count on the
// triples that carry ~29% of all MACs. d1 == d2.
// ---------------------------------------------------------------------------
template<int D3>
__device__ __forceinline__ void compute_diag(const float* xT, const float* Cs,
                                             int l1s, int ls,
                                             int d1, int tid,
                                             float& out_a, float& out_b)
{
    constexpr int P4 = (D3 + 3) / 4;
    constexpr int NP = 2 * P4;
    constexpr int RS = 4 * P4;

    unsigned long long fa[NP], fb[NP];
#pragma unroll
    for (int q = 0; q < NP; q++) {
        const float* b0 = xT + (ls + 2 * q) * XS + tid;
        float a0 = (2 * q     < D3) ? b0[0]        : 0.0f;
        float a1 = (2 * q + 1 < D3) ? b0[XS]       : 0.0f;
        float v0 = (2 * q     < D3) ? b0[TPB]      : 0.0f;
        float v1 = (2 * q + 1 < D3) ? b0[XS + TPB] : 0.0f;
        PACK2(fa[q], a0, a1);
        PACK2(fb[q], v0, v1);
    }

    unsigned long long acc_a = 0ULL, acc_b = 0ULL;
    const float* p1 = xT + l1s * XS + tid;   // F block (== F2 block)
    const int rowstep_i = d1 * RS;           // stride between i-rows (d2 == d1)

    for (int i = 0; i < d1; i++, p1 += XS) {
        unsigned long long ia = 0ULL, ib = 0ULL;

        // ---- j == i term: C(i,i) row, folded by F_i ----
        {
            const float* cr = Cs + (i * d1 + i) * RS;
            unsigned long long saa = 0, sba = 0, sab = 0, sbb = 0;
#pragma unroll
            for (int q = 0; q < P4; q++) {
                float4 c4 = ((const float4*)cr)[q];
                unsigned long long c01, c23;
                PACK2(c01, c4.x, c4.y);
                PACK2(c23, c4.z, c4.w);
                FMA2(saa, c01, fa[2 * q]);
                FMA2(sab, c01, fb[2 * q]);
                FMA2(sba, c23, fa[2 * q + 1]);
                FMA2(sbb, c23, fb[2 * q + 1]);
            }
            unsigned long long da, db;
            DUP2(da, p1[0]);
            DUP2(db, p1[TPB]);
            FMA2(ia, saa, da);
            FMA2(ia, sba, da);
            FMA2(ib, sab, db);
            FMA2(ib, sbb, db);
        }

        // ---- j > i terms: combined row C(i,j)+C(j,i), folded by F_j ----
        const float* p2 = p1 + XS;                        // F_{i+1}
        const float* crA = Cs + (i * d1 + i + 1) * RS;    // C(i, j) row, step RS
        const float* crB = Cs + ((i + 1) * d1 + i) * RS;  // C(j, i) row, step d1*RS
        for (int j = i + 1; j < d1; j++, p2 += XS, crA += RS, crB += rowstep_i) {
            unsigned long long saa = 0, sba = 0, sab = 0, sbb = 0;
#pragma unroll
            for (int q = 0; q < P4; q++) {
                float4 cA = ((const float4*)crA)[q];
                float4 cB = ((const float4*)crB)[q];
                unsigned long long a01, a23, b01, b23, c01, c23;
                PACK2(a01, cA.x, cA.y);
                PACK2(a23, cA.z, cA.w);
                PACK2(b01, cB.x, cB.y);
                PACK2(b23, cB.z, cB.w);
                ADD2(c01, a01, b01);      // symmetrized coefficients
                ADD2(c23, a23, b23);
                FMA2(saa, c01, fa[2 * q]);
                FMA2(sab, c01, fb[2 * q]);
                FMA2(sba, c23, fa[2 * q + 1]);
                FMA2(sbb, c23, fb[2 * q + 1]);
            }
            unsigned long long da, db;
            DUP2(da, p2[0]);
            DUP2(db, p2[TPB]);
            FMA2(ia, saa, da);
            FMA2(ia, sba, da);
            FMA2(ib, sab, db);
            FMA2(ib, sbb, db);
        }

        unsigned long long d1a, d1b;
        DUP2(d1a, p1[0]);
        DUP2(d1b, p1[TPB]);
        FMA2(acc_a, ia, d1a);
        FMA2(acc_b, ib, d1b);
    }

    float alo, ahi, blo, bhi;
    asm("mov.b64 {%0, %1}, %2;" : "=f"(alo), "=f"(ahi) : "l"(acc_a));
    asm("mov.b64 {%0, %1}, %2;" : "=f"(blo), "=f"(bhi) : "l"(acc_b));
    out_a = alo + ahi;
    out_b = blo + bhi;
}

// ---------------------------------------------------------------------------
// Stage compact C block of triple t into smem (rows padded to 4 floats) via
// 4-byte cp.async. Magic-multiply division; divisor==1 cases (magic
// truncates to 0) handled by uniform branch.
// ---------------------------------------------------------------------------
__device__ __forceinline__ void stage_triple(int t, float* buf, const float* cg,
                                             const int* tb_d1, const int* tb_d2,
                                             const int* tb_d3,
                                             const unsigned* tb_m23,
                                             const unsigned* tb_m3, int tid)
{
    int d2  = tb_d2[t], d3 = tb_d3[t];
    int d23 = d2 * d3;
    int total = tb_d1[t] * d23;
    unsigned m23 = tb_m23[t], m3 = tb_m3[t];
    int p4f = (d3 + 3) & ~3;
    const float* src = cg + (size_t)t * (17 * 17 * 17);
    unsigned sbase = smem_addr_u32(buf);

    bool d23_one = (d23 == 1);
    bool d3_one  = (d3 == 1);

    for (int e = tid; e < total; e += TPB) {
        int i   = d23_one ? e : (int)__umulhi((unsigned)e, m23);
        int rem = e - i * d23;
        int j   = d3_one ? rem : (int)__umulhi((unsigned)rem, m3);
        int k   = rem - j * d3;
        unsigned dst = sbase + (unsigned)(((i * d2 + j) * p4f + k) << 2);
        cp_async4(dst, src + i * 289 + j * 17 + k);
    }
}

// ---------------------------------------------------------------------------
// Main kernel
// ---------------------------------------------------------------------------
extern __shared__ char smem_raw[];

__global__ void __launch_bounds__(TPB, 1)
bispec_kernel(const float* __restrict__ x, const float* __restrict__ cg,
              float* __restrict__ out, int B)
{
    float* xT  = (float*)smem_raw;          // [81][513] transposed x tile (512 rows)
    float* cb0 = xT + XT_FL;                // C double buffer
    float* cb1 = cb0 + MAXC;
    int*   tb  = (int*)(cb1 + MAXC);        // triple table (8 arrays of NT)
    int* tb_l1s = tb;
    int* tb_l2s = tb + NT;
    int* tb_ls  = tb + 2 * NT;
    int* tb_d1  = tb + 3 * NT;
    int* tb_d2  = tb + 4 * NT;
    int* tb_d3  = tb + 5 * NT;
    unsigned* tb_m23 = (unsigned*)(tb + 6 * NT);
    unsigned* tb_m3  = (unsigned*)(tb + 7 * NT);

    const int tid = threadIdx.x;
    const int b0  = blockIdx.x * ROWS;

    // Build triple table (must match reference enumeration order)
    if (tid == 0) {
        int n = 0;
        for (int l1 = 0; l1 <= 8; l1++)
            for (int l2 = l1; l2 <= 8; l2++) {
                int lhi = (l1 + l2 < 8) ? (l1 + l2) : 8;
                for (int l = l2 - l1; l <= lhi; l++) {
                    tb_l1s[n] = l1 * l1; tb_l2s[n] = l2 * l2; tb_ls[n] = l * l;
                    int d1 = 2 * l1 + 1, d2 = 2 * l2 + 1, d3 = 2 * l + 1;
                    tb_d1[n] = d1; tb_d2[n] = d2; tb_d3[n] = d3;
                    unsigned d23 = (unsigned)(d2 * d3);
                    // divisor==1 -> magic truncates to 0; stage_triple branches that case
                    tb_m23[n] = (unsigned)((0x100000000ULL + d23 - 1) / d23);
                    tb_m3[n]  = (unsigned)((0x100000000ULL + (unsigned)d3 - 1) / (unsigned)d3);
                    n++;
                }
            }
    }

    // Zero C buffers once: pad slots must always read finite (later they hold
    // stale cg floats, nullified by the zero F3 pack halves)
    for (int i = tid; i < 2 * MAXC; i += TPB) cb0[i] = 0.0f;

    // Stage x tile transposed: xT[c][r] = x[b0+r][c]
    for (int idx = tid; idx < NCOEF * ROWS; idx += TPB) {
        int r = idx / NCOEF;
        int c = idx - r * NCOEF;
        float v = (b0 + r < B) ? x[(size_t)b0 * NCOEF + idx] : 0.0f;
        xT[c * XS + r] = v;
    }
    __syncthreads();

    // Prime the C pipeline
    stage_triple(0, cb0, cg, tb_d1, tb_d2, tb_d3, tb_m23, tb_m3, tid);
    cp_commit();
    cp_wait_all();
    __syncthreads();

    const size_t ob_a = (size_t)(b0 + tid)       * NT;
    const size_t ob_b = (size_t)(b0 + tid + TPB) * NT;
    const bool va = (b0 + tid       < B);
    const bool vb = (b0 + tid + TPB < B);

    for (int t = 0; t < NT; t++) {
        float* cur = (t & 1) ? cb1 : cb0;
        float* nxt = (t & 1) ? cb0 : cb1;

        if (t + 1 < NT)
            stage_triple(t + 1, nxt, cg, tb_d1, tb_d2, tb_d3, tb_m23, tb_m3, tid);
        cp_commit();

        int l1s = tb_l1s[t], l2s = tb_l2s[t], ls = tb_ls[t];
        int d1 = tb_d1[t], d2 = tb_d2[t], d3 = tb_d3[t];
        bool diag = (l1s == l2s);

        float acc_a = 0.0f, acc_b = 0.0f;
        switch (d3) {
            case 1:
                if (diag) compute_diag< 1>(xT, cur, l1s, ls, d1, tid, acc_a, acc_b);
                else      compute_gen < 1>(xT, cur, l1s, l2s, ls, d1, d2, tid, acc_a, acc_b);
                break;
            case 3:
                if (diag) compute_diag< 3>(xT, cur, l1s, ls, d1, tid, acc_a, acc_b);
                else      compute_gen < 3>(xT, cur, l1s, l2s, ls, d1, d2, tid, acc_a, acc_b);
                break;
            case 5:
                if (diag) compute_diag< 5>(xT, cur, l1s, ls, d1, tid, acc_a, acc_b);
                else      compute_gen < 5>(xT, cur, l1s, l2s, ls, d1, d2, tid, acc_a, acc_b);
                break;
            case 7:
                if (diag) compute_diag< 7>(xT, cur, l1s, ls, d1, tid, acc_a, acc_b);
                else      compute_gen < 7>(xT, cur, l1s, l2s, ls, d1, d2, tid, acc_a, acc_b);
                break;
            case 9:
                if (diag) compute_diag< 9>(xT, cur, l1s, ls, d1, tid, acc_a, acc_b);
                else      compute_gen < 9>(xT, cur, l1s, l2s, ls, d1, d2, tid, acc_a, acc_b);
                break;
            case 11:
                if (diag) compute_diag<11>(xT, cur, l1s, ls, d1, tid, acc_a, acc_b);
                else      compute_gen <11>(xT, cur, l1s, l2s, ls, d1, d2, tid, acc_a, acc_b);
                break;
            case 13:
                if (diag) compute_diag<13>(xT, cur, l1s, ls, d1, tid, acc_a, acc_b);
                else      compute_gen <13>(xT, cur, l1s, l2s, ls, d1, d2, tid, acc_a, acc_b);
                break;
            case 15:
                if (diag) compute_diag<15>(xT, cur, l1s, ls, d1, tid, acc_a, acc_b);
                else      compute_gen <15>(xT, cur, l1s, l2s, ls, d1, d2, tid, acc_a, acc_b);
                break;
            default:
                if (diag) compute_diag<17>(xT, cur, l1s, ls, d1, tid, acc_a, acc_b);
                else      compute_gen <17>(xT, cur, l1s, l2s, ls, d1, d2, tid, acc_a, acc_b);
                break;
        }

        // Direct scattered stores: ~900MB L2 sector traffic total, hidden
        // under compute.
        if (va) out[ob_a + t] = acc_a;
        if (vb) out[ob_b + t] = acc_b;

        cp_wait_all();
        __syncthreads();
    }
}

// ---------------------------------------------------------------------------
// Entry point
// ---------------------------------------------------------------------------
extern "C" void kernel_launch(void* const* d_in, const int* in_sizes, int n_in,
                              void* d_out, int out_size)
{
    const float* x  = (const float*)d_in[0];
    const float* cg = (const float*)d_in[1];
    float* out = (float*)d_out;

    int B = in_sizes[0] / NCOEF;
    int grid = (B + ROWS - 1) / ROWS;

    size_t smem_bytes = (size_t)(XT_FL + 2 * MAXC) * sizeof(float)
                      + (size_t)8 * NT * sizeof(int);   // = 219,344 B

    cudaFuncSetAttribute(bispec_kernel,
                         cudaFuncAttributeMaxDynamicSharedMemorySize,
                         (int)smem_bytes);

    bispec_kernel<<<grid, TPB, smem_bytes>>>(x, cg, out, B);
}